// round 17
// baseline (speedup 1.0000x reference)
#include <cuda_runtime.h>

// CRF mean log-likelihood, B=1024, S=1024, T=32.
// Inputs (metadata order): emissions f32 [B,S,T], tags i32 [B,S], mask [B,S]
// (dtype probed at runtime), start f32 [T], transitions f32 [T,T], end f32 [T].
// Output: 1 float.
//
// Per batch: forward warp (head->mid, E) + backward warp (tail->mid, E^T).
// Step: lane = (half h = lane>>4, colpair q = lane&15) computes output cols
// {2q,2q+1} over its 16-t half: 4 broadcast LDS.128 + 16 fma2 (dual E packing:
// accA=(even->u0|odd->u1), accB=(even->u1|odd->u0)) + 1 shfl.xor.b64 combine.
// Emissions stream via cp.async 8-slot ring (LDGSTS, no dest register -> load
// schedule immune to ptxas). Free power-of-2 normalization from p[0]'s
// exponent (in gathered v0); Kacc exact; one final log2f.

#define BATCH   1024
#define SLEN    1024
#define TT      32
#define BPB     7
#define NWARP   (BPB * 2)
#define THREADS (NWARP * 32)               // 448
#define NBLK    ((BATCH + BPB - 1) / BPB)  // 147 -> one wave
#define FULLM   0xffffffffu

__device__ double   g_contrib[BATCH];
__device__ double   g_cnt[BATCH];
__device__ unsigned g_sem = 0;

typedef unsigned long long ull;

__device__ __forceinline__ float ex2f_(float x) { float r; asm("ex2.approx.f32 %0, %1;" : "=f"(r) : "f"(x)); return r; }
__device__ __forceinline__ ull pk2(float lo, float hi) {
    ull r; asm("mov.b64 %0, {%1, %2};" : "=l"(r) : "f"(lo), "f"(hi)); return r;
}
__device__ __forceinline__ void fma2(ull& d, ull a, ull b) {
    asm("fma.rn.f32x2 %0, %1, %2, %0;" : "+l"(d) : "l"(a), "l"(b));
}
__device__ __forceinline__ void add2(ull& d, ull a, ull b) {
    asm("add.rn.f32x2 %0, %1, %2;" : "=l"(d) : "l"(a), "l"(b));
}
__device__ __forceinline__ void mul2(ull& d, ull a, ull b) {
    asm("mul.rn.f32x2 %0, %1, %2;" : "=l"(d) : "l"(a), "l"(b));
}
__device__ __forceinline__ void upk(ull v, float& x, float& y) {
    asm("mov.b64 {%0, %1}, %2;" : "=f"(x), "=f"(y) : "l"(v));
}
__device__ __forceinline__ unsigned smem_u32(const void* p) {
    return (unsigned)__cvta_generic_to_shared(p);
}
#define CP_ASYNC4(sa, ga) asm volatile("cp.async.ca.shared.global [%0], [%1], 4;" :: "r"(sa), "l"(ga))
#define CP_COMMIT()       asm volatile("cp.async.commit_group;" ::: "memory")
#define CP_WAIT7()        asm volatile("cp.async.wait_group 7;" ::: "memory")

// Probe mask dtype from its first bytes (mask[0]=mask[1]=true since len>=256).
__device__ __forceinline__ int probe_mask_mode(const void* m) {
    const unsigned char* u = (const unsigned char*)m;
    if (u[0] != 0 && u[1] != 0) return 0;           // u8 / bool
    if (u[0] == 0) return (u[3] != 0) ? 2 : 4;      // f32 : f64
    return (u[4] != 0) ? 1 : 3;                     // i32 : i64
}
__device__ __forceinline__ bool mask_at(const void* m, int mode, size_t k) {
    switch (mode) {
        case 0:  return ((const unsigned char*)m)[k] != 0;
        case 1:  return ((const int*)m)[k] != 0;
        case 2:  return ((const float*)m)[k] != 0.0f;
        default: { const int* p = (const int*)m; return (p[2*k] | p[2*k+1]) != 0; } // 64-bit
    }
}

// One matvec from buffer (no emission / scale application). Returns combined
// (u0,u1) pair for this lane's colpair, and e0 = biased exp of p[0]
// (valid on half0 lanes only).
__device__ __forceinline__ ull matvec_pair(const float* __restrict__ buf, int h,
                                           const ull* __restrict__ EA,
                                           const ull* __restrict__ EB,
                                           int& e0)
{
    const ulonglong2* pv = (const ulonglong2*)(buf + (h << 4));
    ulonglong2 v0 = pv[0], v1 = pv[1], v2 = pv[2], v3 = pv[3];
    e0 = (int)(((unsigned)v0.x) >> 23);   // p[0] exponent (half0)

    ull a0 = 0ull, a1 = 0ull, b0 = 0ull, b1 = 0ull;
    fma2(a0, v0.x, EA[0]); fma2(b0, v0.x, EB[0]);
    fma2(a1, v0.y, EA[1]); fma2(b1, v0.y, EB[1]);
    fma2(a0, v1.x, EA[2]); fma2(b0, v1.x, EB[2]);
    fma2(a1, v1.y, EA[3]); fma2(b1, v1.y, EB[3]);
    fma2(a0, v2.x, EA[4]); fma2(b0, v2.x, EB[4]);
    fma2(a1, v2.y, EA[5]); fma2(b1, v2.y, EB[5]);
    fma2(a0, v3.x, EA[6]); fma2(b0, v3.x, EB[6]);
    fma2(a1, v3.y, EA[7]); fma2(b1, v3.y, EB[7]);
    add2(a0, a0, a1);
    add2(b0, b0, b1);
    float alo, ahi, blo, bhi;
    upk(a0, alo, ahi);     // alo: even-t -> u0 ; ahi: odd-t -> u1
    upk(b0, blo, bhi);     // blo: even-t -> u1 ; bhi: odd-t -> u0
    ull mine = pk2(alo + bhi, ahi + blo);
    ull other = __shfl_xor_sync(FULLM, mine, 16);
    ull tot; add2(tot, mine, other);
    return tot;
}

// n steps of the scaled recursion in direction DIR. Emissions via cp.async
// ring (8 slots x 128B). p double buffer in smem; only half0 stores.
template<int DIR>
__device__ __forceinline__ void run_chain(
    const float* __restrict__ emb, int jstart, int n,
    int lane, int h, int q,
    const ull* __restrict__ EA, const ull* __restrict__ EB,
    float* __restrict__ buf0, float* __restrict__ buf1,
    float* __restrict__ emring, int& par, int& Kacc)
{
    if (n <= 0) return;
    const float L2E = 1.4426950408889634f;
    const unsigned em_sa = smem_u32(emring) + (unsigned)(lane << 2);

    #define JIDX(s_) ((DIR > 0) ? min(jstart + (s_), SLEN - 1) : max(jstart - (s_), 0))

    // prime 8 slots
    #pragma unroll
    for (int d = 0; d < 8; d++) {
        CP_ASYNC4(em_sa + (unsigned)(d * TT * 4), emb + (size_t)JIDX(d) * TT + lane);
        CP_COMMIT();
    }

    float* pr = (par == 0) ? buf0 : buf1;
    float* pw = (par == 0) ? buf1 : buf0;

    for (int s = 0; s < n; s++) {
        int slot_n = (s + 8) & 7;
        CP_ASYNC4(em_sa + (unsigned)(slot_n * TT * 4), emb + (size_t)JIDX(s + 8) * TT + lane);
        CP_COMMIT();
        CP_WAIT7();
        __syncwarp();

        // emission pair for this colpair (broadcast LDS.64)
        float2 emp = ((const float2*)(emring + (s & 7) * TT))[q];
        float eu0 = ex2f_(emp.x * L2E);
        float eu1 = ex2f_(emp.y * L2E);

        int e0;
        ull tot = matvec_pair(pr, h, EA, EB, e0);
        Kacc += e0 - 127;
        float sc = __int_as_float((254 - e0) << 23);
        ull esc = pk2(eu0 * sc, eu1 * sc);
        ull res; mul2(res, tot, esc);
        if (h == 0) ((ull*)pw)[q] = res;

        float* t_ = pr; pr = pw; pw = t_;
        par ^= 1;
    }
    #undef JIDX
}

__global__ void __launch_bounds__(THREADS)
crf_fused_kernel(const float* __restrict__ em,
                 const int* __restrict__ tags,
                 const void* __restrict__ maskp,
                 const float* __restrict__ startv,
                 const float* __restrict__ transv,
                 const float* __restrict__ endv,
                 float* __restrict__ out)
{
    __shared__ float s_trans[TT * TT];
    __shared__ float s_start[TT];
    __shared__ float s_end[TT];
    __shared__ __align__(16) float s_p[NWARP][2][TT];     // p double buffers
    __shared__ __align__(16) float s_em[NWARP][8][TT];    // cp.async emission rings
    __shared__ __align__(16) float s_bm[BPB][TT];         // B_mid from backward warp
    __shared__ double s_nb[BPB];
    __shared__ int    s_kb[BPB];
    __shared__ double s_r1[NWARP], s_r2[NWARP];
    __shared__ bool   s_last;

    const int  tid   = threadIdx.x;
    const int  w     = tid >> 5;
    const int  lane  = tid & 31;
    const int  h     = lane >> 4;        // t-half
    const int  q     = lane & 15;        // colpair: cols 2q, 2q+1
    const bool isF   = (w < BPB);
    const int  slot  = isF ? w : (w - BPB);
    const int  b     = blockIdx.x * BPB + slot;

    for (int i = tid; i < TT * TT; i += THREADS) s_trans[i] = transv[i];
    if (tid < TT) { s_start[tid] = startv[tid]; s_end[tid] = endv[tid]; }
    __syncthreads();

    const float L2E = 1.4426950408889634f;

    int head = 0, tail = -1, len = 0;
    if (b < BATCH) {
        const int mmode = probe_mask_mode(maskp);
        const size_t mbase = (size_t)b * SLEN;
        int hh = -1;
        #pragma unroll 4
        for (int i = 0; i < SLEN / 32; i++) {
            bool mv = mask_at(maskp, mmode, mbase + i * 32 + lane);
            unsigned bits = __ballot_sync(FULLM, mv);
            len += __popc(bits);
            if (bits) {
                if (hh < 0) hh = i * 32 + (__ffs(bits) - 1);
                tail = i * 32 + 31 - __clz(bits);
            }
        }
        head = (hh < 0) ? 0 : hh;
    }

    const bool active = (b < BATCH) && (len > 0);
    int    KaccF = 0;
    double nsumF = 0.0;
    int    parF = 0;

    if (active) {
        const float* emb = em + (size_t)b * SLEN * TT;
        const int*   tg  = tags + (size_t)b * SLEN;
        const int    mid  = (head + tail) >> 1;
        const bool   hasB = (tail > mid);
        const int    u0 = 2 * q, u1 = 2 * q + 1;

        if (isF) {
            // ---------- FORWARD WARP ----------
            double nsum = 0.0;
            #pragma unroll 4
            for (int j = head + 1 + lane; j <= mid; j += 32) {
                int tj = tg[j], tp = tg[j - 1];
                nsum += (double)s_trans[tp * TT + tj] + (double)emb[j * TT + tj];
            }
            #pragma unroll
            for (int o = 16; o; o >>= 1) nsum += __shfl_xor_sync(FULLM, nsum, o);
            int th = tg[head], tl = tg[tail];
            nsumF = nsum + (double)s_start[th] + (double)emb[head * TT + th] + (double)s_end[tl];

            // E (fwd): dual packings over this lane's t-half and colpair
            ull EA[8], EB[8];
            #pragma unroll
            for (int i = 0; i < 8; i++) {
                int t = h * 16 + 2 * i;
                EA[i] = pk2(expf(s_trans[t * TT + u0]), expf(s_trans[(t + 1) * TT + u1]));
                EB[i] = pk2(expf(s_trans[t * TT + u1]), expf(s_trans[(t + 1) * TT + u0]));
            }

            // init at head
            if (h == 0) {
                float p0 = exp2f((s_start[u0] + emb[head * TT + u0]) * L2E);
                float p1 = exp2f((s_start[u1] + emb[head * TT + u1]) * L2E);
                ((float2*)s_p[w][0])[q] = make_float2(p0, p1);
            }
            run_chain<1>(emb, head + 1, mid - head, lane, h, q, EA, EB,
                         s_p[w][0], s_p[w][1], &s_em[w][0][0], parF, KaccF);
        } else {
            // ---------- BACKWARD WARP ----------
            double nsum = 0.0;
            #pragma unroll 4
            for (int j = mid + 1 + lane; j <= tail; j += 32) {
                int tj = tg[j], tp = tg[j - 1];
                nsum += (double)s_trans[tp * TT + tj] + (double)emb[j * TT + tj];
            }
            #pragma unroll
            for (int o = 16; o; o >>= 1) nsum += __shfl_xor_sync(FULLM, nsum, o);
            if (lane == 0) s_nb[slot] = nsum;

            // E^T (bwd)
            ull EA[8], EB[8];
            #pragma unroll
            for (int i = 0; i < 8; i++) {
                int t = h * 16 + 2 * i;
                EA[i] = pk2(expf(s_trans[u0 * TT + t]), expf(s_trans[u1 * TT + t + 1]));
                EB[i] = pk2(expf(s_trans[u1 * TT + t]), expf(s_trans[u0 * TT + t + 1]));
            }

            int KaccB = 0;
            if (hasB) {
                if (h == 0) {
                    float p0 = ex2f_(emb[tail * TT + u0] * L2E) * expf(s_end[u0]);
                    float p1 = ex2f_(emb[tail * TT + u1] * L2E) * expf(s_end[u1]);
                    ((float2*)s_p[w][0])[q] = make_float2(p0, p1);
                }
                int par = 0;
                run_chain<-1>(emb, tail - 1, tail - mid - 1, lane, h, q, EA, EB,
                              s_p[w][0], s_p[w][1], &s_em[w][0][0], par, KaccB);
                // final dot (no emission), normalized by free e0
                __syncwarp();
                int e0;
                ull tot = matvec_pair(s_p[w][par], h, EA, EB, e0);
                KaccB += e0 - 127;
                float sc = __int_as_float((254 - e0) << 23);
                ull bm; mul2(bm, tot, pk2(sc, sc));
                if (h == 0) ((ull*)s_bm[slot])[q] = bm;
            } else {
                if (h == 0)
                    ((float2*)s_bm[slot])[q] = make_float2(expf(s_end[u0]), expf(s_end[u1]));
            }
            if (lane == 0) s_kb[slot] = KaccB;
        }
    } else if (b < BATCH && isF && lane == 0) {
        g_contrib[b] = 0.0; g_cnt[b] = 0.0;
    }

    __syncthreads();   // backward results (s_bm, s_nb, s_kb) visible

    if (active && isF) {
        float alpha = s_p[w][parF][lane];
        float vv = alpha * s_bm[slot][lane];
        #pragma unroll
        for (int o = 16; o; o >>= 1) vv += __shfl_xor_sync(FULLM, vv, o);
        const double LN2 = 0.6931471805599453;
        double denom = ((double)KaccF + (double)s_kb[slot] + (double)log2f(vv)) * LN2;
        double num   = nsumF + s_nb[slot];
        if (lane == 0) {
            g_contrib[b] = (denom - num) / ((double)len + 1e-6);
            g_cnt[b]     = 1.0;
        }
    }

    // ---- last-block-done fused reduction (deterministic fixed order) ----
    __syncthreads();
    if (tid == 0) {
        __threadfence();
        s_last = (atomicAdd(&g_sem, 1u) == (unsigned)(gridDim.x - 1));
    }
    __syncthreads();
    if (s_last) {
        __threadfence();
        double a = 0.0, c = 0.0;
        for (int i = tid; i < BATCH; i += THREADS) { a += g_contrib[i]; c += g_cnt[i]; }
        #pragma unroll
        for (int o = 16; o; o >>= 1) {
            a += __shfl_xor_sync(FULLM, a, o);
            c += __shfl_xor_sync(FULLM, c, o);
        }
        if (lane == 0) { s_r1[w] = a; s_r2[w] = c; }
        __syncthreads();
        if (tid == 0) {
            double A = 0.0, C = 0.0;
            for (int i = 0; i < NWARP; i++) { A += s_r1[i]; C += s_r2[i]; }
            out[0] = (float)(A / (C + 1e-6));
            g_sem = 0;   // re-arm for next graph replay
        }
    }
}

extern "C" void kernel_launch(void* const* d_in, const int* in_sizes, int n_in,
                              void* d_out, int out_size)
{
    const float* em    = (const float*)d_in[0];
    const int*   tags  = (const int*)d_in[1];
    const void*  mask  = (const void*)d_in[2];
    const float* st    = (const float*)d_in[3];
    const float* tr    = (const float*)d_in[4];
    const float* en    = (const float*)d_in[5];

    crf_fused_kernel<<<NBLK, THREADS>>>(em, tags, mask, st, tr, en, (float*)d_out);
}